// round 10
// baseline (speedup 1.0000x reference)
#include <cuda_runtime.h>
#include <cuda_bf16.h>
#include <cstdint>
#include <cstddef>

#define BATCH 4096
#define DIM   1024
#define TDICT 32768
#define TOPK  64
#define CAND_MAX 512

#define SX 21.0f              // x quant scale (max|x| ~5.3 -> <=112)
#define SW 1600.0f            // w quant scale (|w| <= 0.0766 -> <=123)
#define INV_S (1.0f / (SX * SW))
#define MARGIN 0.3f

// ---------------- scratch (device globals) ----------------------------------
__device__ __nv_bfloat16 g_actsb[(size_t)BATCH * TDICT];   // approx acts, 256 MB
__device__ float         g_xc[(size_t)BATCH * DIM];        // centered x fp32
__device__ int8_t        g_xq[(size_t)BATCH * DIM];        // centered x int8
__device__ float         g_Wt[(size_t)TDICT * DIM];        // W^T fp32
__device__ int8_t        g_wq[(size_t)TDICT * DIM];        // W^T int8
__device__ int   g_cand[(size_t)BATCH * CAND_MAX];
__device__ int   g_ccnt[BATCH];
__device__ int   g_tidx[BATCH * TOPK];
__device__ float g_tval[BATCH * TOPK];

// ---------------- helpers ---------------------------------------------------
__device__ __forceinline__ uint32_t smem_u32(const void* p) {
    uint32_t a;
    asm("{ .reg .u64 t; cvta.to.shared.u64 t, %1; cvt.u32.u64 %0, t; }" : "=r"(a) : "l"(p));
    return a;
}
__device__ __forceinline__ void cp16(uint32_t dst, const void* src) {
    asm volatile("cp.async.cg.shared.global [%0], [%1], 16;" :: "r"(dst), "l"(src));
}
__device__ __forceinline__ void ldsm4(uint32_t& r0, uint32_t& r1, uint32_t& r2,
                                      uint32_t& r3, uint32_t addr) {
    asm volatile("ldmatrix.sync.aligned.m8n8.x4.shared.b16 {%0,%1,%2,%3}, [%4];"
                 : "=r"(r0), "=r"(r1), "=r"(r2), "=r"(r3) : "r"(addr));
}
// int8 MMA: same fragment byte-offsets as bf16 m16n8k16 (pairs of s8 == one b16)
__device__ __forceinline__ void mma16832s8(int* c, const uint32_t* a,
                                           const uint32_t* b) {
    asm volatile(
        "mma.sync.aligned.m16n8k32.row.col.s32.s8.s8.s32 "
        "{%0,%1,%2,%3}, {%4,%5,%6,%7}, {%8,%9}, {%0,%1,%2,%3};"
        : "+r"(c[0]), "+r"(c[1]), "+r"(c[2]), "+r"(c[3])
        : "r"(a[0]), "r"(a[1]), "r"(a[2]), "r"(a[3]), "r"(b[0]), "r"(b[1]));
}
__device__ __forceinline__ int8_t q8(float v, float s) {
    int q = __float2int_rn(v * s);
    q = q > 127 ? 127 : (q < -127 ? -127 : q);
    return (int8_t)q;
}

// ---------------- kernel 1: center x -> fp32 + int8 -------------------------
__global__ void split_x_kernel(const float* __restrict__ x,
                               const float* __restrict__ b_dec) {
    int i = blockIdx.x * 256 + threadIdx.x;
    float v = x[i] - b_dec[i & (DIM - 1)];
    g_xc[i] = v;
    g_xq[i] = q8(v, SX);
}

// ---------------- kernel 2: transpose W_enc -> fp32 + int8 ------------------
__global__ __launch_bounds__(256, 4)
void split_w_kernel(const float* __restrict__ W) {
    __shared__ float tile[32][33];
    const int n0 = blockIdx.x * 32, k0 = blockIdx.y * 32;
    const int tx = threadIdx.x & 31, ty = threadIdx.x >> 5;
#pragma unroll
    for (int i = 0; i < 4; i++)
        tile[ty + 8 * i][tx] = W[(size_t)(k0 + ty + 8 * i) * TDICT + n0 + tx];
    __syncthreads();
    const int r = threadIdx.x >> 3, c0 = (threadIdx.x & 7) * 4;
#pragma unroll
    for (int i = 0; i < 4; i++) {
        float v = tile[c0 + i][r];
        size_t o = (size_t)(n0 + r) * DIM + k0 + c0 + i;
        g_Wt[o] = v;
        g_wq[o] = q8(v, SW);
    }
}

// ---------------- kernel 3: int8 IMMA GEMM 128x128, BK=64, 2-stage ----------
// smem rows: 64B payload + 16B pad = 80B (ldmatrix conflict-free).
#define AROWB 80
#define TILEB (128 * AROWB)

__global__ __launch_bounds__(256, 2)
void igemm_kernel(const float* __restrict__ bias) {
    __shared__ __align__(16) uint8_t sA[2][TILEB];
    __shared__ __align__(16) uint8_t sB[2][TILEB];

    const int tid = threadIdx.x, lane = tid & 31, wid = tid >> 5;
    const int m0 = blockIdx.x * 128, n0 = blockIdx.y * 128;
    const int wm = (wid >> 2) * 64, wn = (wid & 3) * 32;

    int c[4][4][4];
#pragma unroll
    for (int i = 0; i < 4; i++)
#pragma unroll
        for (int j = 0; j < 4; j++)
#pragma unroll
            for (int k = 0; k < 4; k++) c[i][j][k] = 0;

    const uint32_t uA0 = smem_u32(sA[0]), uB0 = smem_u32(sB[0]);

    // stage loader: 128 rows x 4 chunks(16B) each for A and B (64B = k64 int8)
    auto load_tile = [&](int buf, int k0) {
        const uint32_t ab = uA0 + buf * TILEB, bb = uB0 + buf * TILEB;
#pragma unroll
        for (int i = 0; i < 2; i++) {
            int id = tid + 256 * i;
            int row = id >> 2, ch = id & 3;
            cp16(ab + row * AROWB + ch * 16,
                 g_xq + (size_t)(m0 + row) * DIM + k0 + ch * 16);
            cp16(bb + row * AROWB + ch * 16,
                 g_wq + (size_t)(n0 + row) * DIM + k0 + ch * 16);
        }
        asm volatile("cp.async.commit_group;" ::: "memory");
    };

    load_tile(0, 0);

    for (int s = 0; s < DIM / 64; s++) {          // 16 stages
        if (s + 1 < DIM / 64) {
            load_tile((s + 1) & 1, (s + 1) * 64);
            asm volatile("cp.async.wait_group 1;" ::: "memory");
        } else {
            asm volatile("cp.async.wait_group 0;" ::: "memory");
        }
        __syncthreads();

        const uint32_t ab = uA0 + (s & 1) * TILEB, bb = uB0 + (s & 1) * TILEB;
#pragma unroll
        for (int ks = 0; ks < 2; ks++) {          // 2 x k32
            uint32_t a[4][4];
#pragma unroll
            for (int mt = 0; mt < 4; mt++) {
                uint32_t addr = ab + (wm + mt * 16 + (lane & 15)) * AROWB +
                                ks * 32 + ((lane >> 4) << 4);
                ldsm4(a[mt][0], a[mt][1], a[mt][2], a[mt][3], addr);
            }
            uint32_t b[4][2];
#pragma unroll
            for (int nh = 0; nh < 2; nh++) {
                uint32_t addr = bb +
                    (wn + nh * 16 + ((lane & 16) >> 1) + (lane & 7)) * AROWB +
                    ks * 32 + (((lane >> 3) & 1) << 4);
                uint32_t r0, r1, r2, r3;
                ldsm4(r0, r1, r2, r3, addr);
                b[nh * 2 + 0][0] = r0; b[nh * 2 + 0][1] = r1;
                b[nh * 2 + 1][0] = r2; b[nh * 2 + 1][1] = r3;
            }
#pragma unroll
            for (int mt = 0; mt < 4; mt++)
#pragma unroll
                for (int nt = 0; nt < 4; nt++)
                    mma16832s8(c[mt][nt], a[mt], b[nt]);
        }
        __syncthreads();
    }

    // epilogue: dequant + bias + relu -> bf16
#pragma unroll
    for (int mt = 0; mt < 4; mt++) {
        const int row = m0 + wm + mt * 16 + (lane >> 2);
#pragma unroll
        for (int nt = 0; nt < 4; nt++) {
            const int col = n0 + wn + nt * 8 + (lane & 3) * 2;
            const float b0 = bias[col], b1 = bias[col + 1];
            __nv_bfloat162 p0, p1;
            p0.x = __float2bfloat16_rn(fmaxf((float)c[mt][nt][0] * INV_S + b0, 0.f));
            p0.y = __float2bfloat16_rn(fmaxf((float)c[mt][nt][1] * INV_S + b1, 0.f));
            p1.x = __float2bfloat16_rn(fmaxf((float)c[mt][nt][2] * INV_S + b0, 0.f));
            p1.y = __float2bfloat16_rn(fmaxf((float)c[mt][nt][3] * INV_S + b1, 0.f));
            *reinterpret_cast<__nv_bfloat162*>(
                g_actsb + (size_t)row * TDICT + col) = p0;
            *reinterpret_cast<__nv_bfloat162*>(
                g_actsb + (size_t)(row + 8) * TDICT + col) = p1;
        }
    }
}

// ---------------- kernel 4: approx 64th value + candidate collection --------
// Streaming global passes (no smem staging): pass2/3 hit L2.
__global__ __launch_bounds__(512, 3)
void topk_approx_kernel() {
    __shared__ unsigned int hist[256], suf[256];
    __shared__ unsigned int s_b1, s_kneed;
    __shared__ float s_cut;
    __shared__ int scnt;

    const int tid = threadIdx.x, row = blockIdx.x, lane = tid & 31;
    const uint4* src = reinterpret_cast<const uint4*>(g_actsb + (size_t)row * TDICT);

    if (tid < 256) hist[tid] = 0;
    __syncthreads();

    // pass 1: high-byte histogram, warp-aggregated atomics
    for (int i = tid; i < TDICT / 8; i += 512) {
        uint4 v = src[i];
        unsigned int ws[4] = {v.x, v.y, v.z, v.w};
#pragma unroll
        for (int j = 0; j < 4; j++) {
            unsigned int h0 = (ws[j] >> 8) & 0xFFu;
            unsigned int h1 = ws[j] >> 24;
            unsigned int m0 = __match_any_sync(0xffffffffu, h0);
            if (lane == (__ffs(m0) - 1)) atomicAdd(&hist[h0], __popc(m0));
            unsigned int m1 = __match_any_sync(0xffffffffu, h1);
            if (lane == (__ffs(m1) - 1)) atomicAdd(&hist[h1], __popc(m1));
        }
    }
    __syncthreads();
    if (tid < 256) suf[tid] = hist[tid];
    __syncthreads();
#pragma unroll
    for (int off = 1; off < 256; off <<= 1) {
        unsigned int add = 0;
        if (tid < 256 && tid + off < 256) add = suf[tid + off];
        __syncthreads();
        if (tid < 256) suf[tid] += add;
        __syncthreads();
    }
    if (tid < 256) {
        unsigned int hi = (tid == 255) ? 0u : suf[tid + 1];
        if (suf[tid] >= TOPK && hi < TOPK) { s_b1 = tid; s_kneed = TOPK - hi; }
    }
    __syncthreads();
    const unsigned int b1 = s_b1, kneed = s_kneed;
    if (tid < 256) hist[tid] = 0;
    __syncthreads();

    // pass 2: low byte within bin b1 (row now in L2)
    for (int i = tid; i < TDICT / 8; i += 512) {
        uint4 v = src[i];
        unsigned int ws[4] = {v.x, v.y, v.z, v.w};
#pragma unroll
        for (int j = 0; j < 4; j++) {
            unsigned int lo = ws[j] & 0xFFFFu, hi2 = ws[j] >> 16;
            if ((lo >> 8) == b1) atomicAdd(&hist[lo & 0xFFu], 1u);
            if ((hi2 >> 8) == b1) atomicAdd(&hist[hi2 & 0xFFu], 1u);
        }
    }
    __syncthreads();
    if (tid < 256) suf[tid] = hist[tid];
    __syncthreads();
#pragma unroll
    for (int off = 1; off < 256; off <<= 1) {
        unsigned int add = 0;
        if (tid < 256 && tid + off < 256) add = suf[tid + off];
        __syncthreads();
        if (tid < 256) suf[tid] += add;
        __syncthreads();
    }
    if (tid < 256) {
        unsigned int hi = (tid == 255) ? 0u : suf[tid + 1];
        if (suf[tid] >= kneed && hi < kneed) {
            unsigned int thr = (b1 << 8) | (unsigned)tid;
            s_cut = fmaxf(__uint_as_float(thr << 16) - MARGIN, 0.0f);
            scnt = 0;
        }
    }
    __syncthreads();

    // pass 3: collect candidates above cut
    const float cut = s_cut;
    for (int i = tid; i < TDICT / 8; i += 512) {
        uint4 v = src[i];
        unsigned int ws[4] = {v.x, v.y, v.z, v.w};
#pragma unroll
        for (int j = 0; j < 4; j++) {
#pragma unroll
            for (int h = 0; h < 2; h++) {
                unsigned int u = (h == 0) ? (ws[j] & 0xFFFFu) : (ws[j] >> 16);
                float f = __uint_as_float(u << 16);
                if (f > cut) {
                    int p = atomicAdd(&scnt, 1);
                    if (p < CAND_MAX)
                        g_cand[(size_t)row * CAND_MAX + p] = i * 8 + j * 2 + h;
                }
            }
        }
    }
    __syncthreads();
    if (tid == 0) g_ccnt[row] = scnt < CAND_MAX ? scnt : CAND_MAX;
}

// ---------------- kernel 5: exact fp32 refinement + exact top-64 ------------
__global__ __launch_bounds__(256, 1)
void refine_kernel(const float* __restrict__ bias) {
    __shared__ float xs[DIM];
    __shared__ unsigned long long skey[CAND_MAX];
    __shared__ float svv[CAND_MAX];
    __shared__ int   sidx[CAND_MAX];

    const int row = blockIdx.x, tid = threadIdx.x;
    const int lane = tid & 31, wid = tid >> 5;
    for (int i = tid; i < DIM; i += 256) xs[i] = g_xc[(size_t)row * DIM + i];
    const int cnt = g_ccnt[row];
    __syncthreads();

    for (int c = wid; c < cnt; c += 8) {
        const int idx = g_cand[(size_t)row * CAND_MAX + c];
        const float* w = g_Wt + (size_t)idx * DIM;
        float a0 = 0.f, a1 = 0.f, a2 = 0.f, a3 = 0.f;
#pragma unroll
        for (int j = 0; j < DIM; j += 128) {
            a0 += xs[j + lane]      * __ldg(w + j + lane);
            a1 += xs[j + lane + 32] * __ldg(w + j + lane + 32);
            a2 += xs[j + lane + 64] * __ldg(w + j + lane + 64);
            a3 += xs[j + lane + 96] * __ldg(w + j + lane + 96);
        }
        float acc = (a0 + a1) + (a2 + a3);
#pragma unroll
        for (int o = 16; o > 0; o >>= 1)
            acc += __shfl_xor_sync(0xffffffffu, acc, o);
        if (lane == 0) {
            float v = fmaxf(acc + bias[idx], 0.f);
            skey[c] = ((unsigned long long)__float_as_uint(v) << 32) |
                      (unsigned)(0xFFFFFFFFu - (unsigned)idx);
            svv[c] = v;
            sidx[c] = idx;
        }
    }
    __syncthreads();

    for (int c = tid; c < cnt; c += 256) {
        const unsigned long long k = skey[c];
        int r = 0;
        for (int j = 0; j < cnt; j++) r += (skey[j] > k);
        if (r < TOPK) {
            g_tidx[row * TOPK + r] = sidx[c];
            g_tval[row * TOPK + r] = svv[c];
        }
    }
}

// ---------------- kernel 6: nested group decode -----------------------------
__global__ __launch_bounds__(256, 1)
void decode_kernel(const float* __restrict__ Wd, const float* __restrict__ bdec,
                   float* __restrict__ out) {
    __shared__ int   sidx[TOPK];
    __shared__ float sval[TOPK];
    const int row = blockIdx.x, tid = threadIdx.x;
    if (tid < TOPK) {
        sidx[tid] = g_tidx[row * TOPK + tid];
        sval[tid] = g_tval[row * TOPK + tid];
    }
    __syncthreads();

    float acc[4];
#pragma unroll
    for (int j = 0; j < 4; j++) acc[j] = bdec[tid + j * 256];

    const int bounds[4] = {0, 2048, 8192, TDICT};
#pragma unroll
    for (int g = 0; g < 3; g++) {
        for (int t = 0; t < TOPK; t++) {
            const int idx = sidx[t];
            if (idx >= bounds[g] && idx < bounds[g + 1]) {
                const float v = sval[t];
                const float* w = Wd + (size_t)idx * DIM;
#pragma unroll
                for (int j = 0; j < 4; j++) acc[j] += v * w[tid + j * 256];
            }
        }
        const size_t o = ((size_t)g * BATCH + row) * DIM;
#pragma unroll
        for (int j = 0; j < 4; j++) out[o + tid + j * 256] = acc[j];
    }
}

// ---------------- launch ----------------------------------------------------
extern "C" void kernel_launch(void* const* d_in, const int* in_sizes, int n_in,
                              void* d_out, int out_size) {
    const float* x     = (const float*)d_in[0];
    const float* W_enc = (const float*)d_in[1];
    const float* b_enc = (const float*)d_in[2];
    const float* W_dec = (const float*)d_in[3];
    const float* b_dec = (const float*)d_in[4];
    float* out = (float*)d_out;

    split_x_kernel<<<BATCH * DIM / 256, 256>>>(x, b_dec);
    split_w_kernel<<<dim3(TDICT / 32, DIM / 32), 256>>>(W_enc);

    igemm_kernel<<<dim3(BATCH / 128, TDICT / 128), 256>>>(b_enc);

    topk_approx_kernel<<<BATCH, 512>>>();
    refine_kernel<<<BATCH, 256>>>(b_enc);

    decode_kernel<<<BATCH, 256>>>(W_dec, b_dec, out);
}

// round 11
// speedup vs baseline: 1.5261x; 1.5261x over previous
#include <cuda_runtime.h>
#include <cuda_bf16.h>
#include <cstdint>
#include <cstddef>

#define BATCH 4096
#define DIM   1024
#define TDICT 32768
#define TOPK  64
#define CAND_MAX 512
#define MARGIN 0.15f

#define NCHUNK 4
#define CHUNK (BATCH / NCHUNK)       // 1024 rows

// ---------------- scratch (device globals) ----------------------------------
__device__ __nv_bfloat16 g_actsb[(size_t)BATCH * TDICT];   // approx acts, 256 MB
__device__ float         g_xc[(size_t)BATCH * DIM];        // centered x fp32
__device__ __nv_bfloat16 g_xb[(size_t)BATCH * DIM];        // centered x bf16
__device__ float         g_Wt[(size_t)TDICT * DIM];        // W^T fp32
__device__ __nv_bfloat16 g_Wb[(size_t)TDICT * DIM];        // W^T bf16
__device__ int   g_cand[(size_t)BATCH * CAND_MAX];
__device__ int   g_ccnt[BATCH];
__device__ int   g_tidx[BATCH * TOPK];
__device__ float g_tval[BATCH * TOPK];

// ---------------- helpers ---------------------------------------------------
__device__ __forceinline__ uint32_t smem_u32(const void* p) {
    uint32_t a;
    asm("{ .reg .u64 t; cvta.to.shared.u64 t, %1; cvt.u32.u64 %0, t; }" : "=r"(a) : "l"(p));
    return a;
}
__device__ __forceinline__ void cp16(uint32_t dst, const void* src) {
    asm volatile("cp.async.cg.shared.global [%0], [%1], 16;" :: "r"(dst), "l"(src));
}
__device__ __forceinline__ void ldsm4(uint32_t& r0, uint32_t& r1, uint32_t& r2,
                                      uint32_t& r3, uint32_t addr) {
    asm volatile("ldmatrix.sync.aligned.m8n8.x4.shared.b16 {%0,%1,%2,%3}, [%4];"
                 : "=r"(r0), "=r"(r1), "=r"(r2), "=r"(r3) : "r"(addr));
}
__device__ __forceinline__ void mma16816(float* c, const uint32_t* a,
                                         const uint32_t* b) {
    asm volatile(
        "mma.sync.aligned.m16n8k16.row.col.f32.bf16.bf16.f32 "
        "{%0,%1,%2,%3}, {%4,%5,%6,%7}, {%8,%9}, {%0,%1,%2,%3};"
        : "+f"(c[0]), "+f"(c[1]), "+f"(c[2]), "+f"(c[3])
        : "r"(a[0]), "r"(a[1]), "r"(a[2]), "r"(a[3]), "r"(b[0]), "r"(b[1]));
}

// ---------------- kernel 1: center x -> fp32 + bf16 -------------------------
__global__ void split_x_kernel(const float* __restrict__ x,
                               const float* __restrict__ b_dec) {
    int i = blockIdx.x * 256 + threadIdx.x;
    float v = x[i] - b_dec[i & (DIM - 1)];
    g_xc[i] = v;
    g_xb[i] = __float2bfloat16_rn(v);
}

// ---------------- kernel 2: transpose W_enc -> fp32 + bf16 ------------------
__global__ __launch_bounds__(256, 4)
void split_w_kernel(const float* __restrict__ W) {
    __shared__ float tile[32][33];
    const int n0 = blockIdx.x * 32, k0 = blockIdx.y * 32;
    const int tx = threadIdx.x & 31, ty = threadIdx.x >> 5;
#pragma unroll
    for (int i = 0; i < 4; i++)
        tile[ty + 8 * i][tx] = W[(size_t)(k0 + ty + 8 * i) * TDICT + n0 + tx];
    __syncthreads();
    const int r = threadIdx.x >> 3, c0 = (threadIdx.x & 7) * 4;
#pragma unroll
    for (int i = 0; i < 4; i++) {
        float v = tile[c0 + i][r];
        size_t o = (size_t)(n0 + r) * DIM + k0 + c0 + i;
        g_Wt[o] = v;
        g_Wb[o] = __float2bfloat16_rn(v);
    }
}

// ---------------- kernel 3: bf16 HMMA GEMM 128x128, BK=32, occ 2 (R7) -------
#define AROWB 80
#define TILEB (128 * AROWB)

__global__ __launch_bounds__(256, 2)
void hgemm_kernel(const float* __restrict__ bias, int mbase) {
    __shared__ __align__(16) uint8_t sA[2][TILEB];
    __shared__ __align__(16) uint8_t sB[2][TILEB];

    const int tid = threadIdx.x, lane = tid & 31, wid = tid >> 5;
    const int m0 = mbase + blockIdx.x * 128, n0 = blockIdx.y * 128;
    const int wm = (wid >> 2) * 64, wn = (wid & 3) * 32;

    float c[4][4][4];
#pragma unroll
    for (int i = 0; i < 4; i++)
#pragma unroll
        for (int j = 0; j < 4; j++)
#pragma unroll
            for (int k = 0; k < 4; k++) c[i][j][k] = 0.f;

    const uint32_t uA0 = smem_u32(sA[0]), uB0 = smem_u32(sB[0]);

    auto load_tile = [&](int buf, int k0) {
        const uint32_t ab = uA0 + buf * TILEB, bb = uB0 + buf * TILEB;
#pragma unroll
        for (int i = 0; i < 2; i++) {
            int id = tid + 256 * i;
            int row = id >> 2, ch = id & 3;
            cp16(ab + row * AROWB + ch * 16,
                 (const char*)(g_xb + (size_t)(m0 + row) * DIM + k0) + ch * 16);
            cp16(bb + row * AROWB + ch * 16,
                 (const char*)(g_Wb + (size_t)(n0 + row) * DIM + k0) + ch * 16);
        }
        asm volatile("cp.async.commit_group;" ::: "memory");
    };

    load_tile(0, 0);

    for (int s = 0; s < DIM / 32; s++) {
        if (s + 1 < DIM / 32) {
            load_tile((s + 1) & 1, (s + 1) * 32);
            asm volatile("cp.async.wait_group 1;" ::: "memory");
        } else {
            asm volatile("cp.async.wait_group 0;" ::: "memory");
        }
        __syncthreads();

        const uint32_t ab = uA0 + (s & 1) * TILEB, bb = uB0 + (s & 1) * TILEB;
#pragma unroll
        for (int ks = 0; ks < 2; ks++) {
            uint32_t a[4][4];
#pragma unroll
            for (int mt = 0; mt < 4; mt++) {
                uint32_t addr = ab + (wm + mt * 16 + (lane & 15)) * AROWB +
                                ks * 32 + ((lane >> 4) << 4);
                ldsm4(a[mt][0], a[mt][1], a[mt][2], a[mt][3], addr);
            }
            uint32_t b[4][2];
#pragma unroll
            for (int nh = 0; nh < 2; nh++) {
                uint32_t addr = bb +
                    (wn + nh * 16 + ((lane & 16) >> 1) + (lane & 7)) * AROWB +
                    ks * 32 + (((lane >> 3) & 1) << 4);
                uint32_t r0, r1, r2, r3;
                ldsm4(r0, r1, r2, r3, addr);
                b[nh * 2 + 0][0] = r0; b[nh * 2 + 0][1] = r1;
                b[nh * 2 + 1][0] = r2; b[nh * 2 + 1][1] = r3;
            }
#pragma unroll
            for (int mt = 0; mt < 4; mt++)
#pragma unroll
                for (int nt = 0; nt < 4; nt++)
                    mma16816(c[mt][nt], a[mt], b[nt]);
        }
        __syncthreads();
    }

#pragma unroll
    for (int mt = 0; mt < 4; mt++) {
        const int row = m0 + wm + mt * 16 + (lane >> 2);
#pragma unroll
        for (int nt = 0; nt < 4; nt++) {
            const int col = n0 + wn + nt * 8 + (lane & 3) * 2;
            const float b0 = bias[col], b1 = bias[col + 1];
            __nv_bfloat162 p0, p1;
            p0.x = __float2bfloat16_rn(fmaxf(c[mt][nt][0] + b0, 0.f));
            p0.y = __float2bfloat16_rn(fmaxf(c[mt][nt][1] + b1, 0.f));
            p1.x = __float2bfloat16_rn(fmaxf(c[mt][nt][2] + b0, 0.f));
            p1.y = __float2bfloat16_rn(fmaxf(c[mt][nt][3] + b1, 0.f));
            *reinterpret_cast<__nv_bfloat162*>(
                g_actsb + (size_t)row * TDICT + col) = p0;
            *reinterpret_cast<__nv_bfloat162*>(
                g_actsb + (size_t)(row + 8) * TDICT + col) = p1;
        }
    }
}

// ---------------- kernel 4: approx 64th value + candidates (streaming) ------
__global__ __launch_bounds__(512, 3)
void topk_approx_kernel(int rbase) {
    __shared__ unsigned int hist[256], suf[256];
    __shared__ unsigned int s_b1, s_kneed;
    __shared__ float s_cut;
    __shared__ int scnt;

    const int tid = threadIdx.x, row = rbase + blockIdx.x, lane = tid & 31;
    const uint4* src = reinterpret_cast<const uint4*>(g_actsb + (size_t)row * TDICT);

    if (tid < 256) hist[tid] = 0;
    __syncthreads();

    for (int i = tid; i < TDICT / 8; i += 512) {
        uint4 v = src[i];
        unsigned int ws[4] = {v.x, v.y, v.z, v.w};
#pragma unroll
        for (int j = 0; j < 4; j++) {
            unsigned int h0 = (ws[j] >> 8) & 0xFFu;
            unsigned int h1 = ws[j] >> 24;
            unsigned int m0 = __match_any_sync(0xffffffffu, h0);
            if (lane == (__ffs(m0) - 1)) atomicAdd(&hist[h0], __popc(m0));
            unsigned int m1 = __match_any_sync(0xffffffffu, h1);
            if (lane == (__ffs(m1) - 1)) atomicAdd(&hist[h1], __popc(m1));
        }
    }
    __syncthreads();
    if (tid < 256) suf[tid] = hist[tid];
    __syncthreads();
#pragma unroll
    for (int off = 1; off < 256; off <<= 1) {
        unsigned int add = 0;
        if (tid < 256 && tid + off < 256) add = suf[tid + off];
        __syncthreads();
        if (tid < 256) suf[tid] += add;
        __syncthreads();
    }
    if (tid < 256) {
        unsigned int hi = (tid == 255) ? 0u : suf[tid + 1];
        if (suf[tid] >= TOPK && hi < TOPK) { s_b1 = tid; s_kneed = TOPK - hi; }
    }
    __syncthreads();
    const unsigned int b1 = s_b1, kneed = s_kneed;
    if (tid < 256) hist[tid] = 0;
    __syncthreads();

    for (int i = tid; i < TDICT / 8; i += 512) {
        uint4 v = src[i];
        unsigned int ws[4] = {v.x, v.y, v.z, v.w};
#pragma unroll
        for (int j = 0; j < 4; j++) {
            unsigned int lo = ws[j] & 0xFFFFu, hi2 = ws[j] >> 16;
            if ((lo >> 8) == b1) atomicAdd(&hist[lo & 0xFFu], 1u);
            if ((hi2 >> 8) == b1) atomicAdd(&hist[hi2 & 0xFFu], 1u);
        }
    }
    __syncthreads();
    if (tid < 256) suf[tid] = hist[tid];
    __syncthreads();
#pragma unroll
    for (int off = 1; off < 256; off <<= 1) {
        unsigned int add = 0;
        if (tid < 256 && tid + off < 256) add = suf[tid + off];
        __syncthreads();
        if (tid < 256) suf[tid] += add;
        __syncthreads();
    }
    if (tid < 256) {
        unsigned int hi = (tid == 255) ? 0u : suf[tid + 1];
        if (suf[tid] >= kneed && hi < kneed) {
            unsigned int thr = (b1 << 8) | (unsigned)tid;
            s_cut = fmaxf(__uint_as_float(thr << 16) - MARGIN, 0.0f);
            scnt = 0;
        }
    }
    __syncthreads();

    const float cut = s_cut;
    for (int i = tid; i < TDICT / 8; i += 512) {
        uint4 v = src[i];
        unsigned int ws[4] = {v.x, v.y, v.z, v.w};
#pragma unroll
        for (int j = 0; j < 4; j++) {
#pragma unroll
            for (int h = 0; h < 2; h++) {
                unsigned int u = (h == 0) ? (ws[j] & 0xFFFFu) : (ws[j] >> 16);
                float f = __uint_as_float(u << 16);
                if (f > cut) {
                    int p = atomicAdd(&scnt, 1);
                    if (p < CAND_MAX)
                        g_cand[(size_t)row * CAND_MAX + p] = i * 8 + j * 2 + h;
                }
            }
        }
    }
    __syncthreads();
    if (tid == 0) g_ccnt[row] = scnt < CAND_MAX ? scnt : CAND_MAX;
}

// ---------------- kernel 5: exact fp32 refinement + exact top-64 ------------
__global__ __launch_bounds__(256, 1)
void refine_kernel(const float* __restrict__ bias, int rbase) {
    __shared__ float xs[DIM];
    __shared__ unsigned long long skey[CAND_MAX];
    __shared__ float svv[CAND_MAX];
    __shared__ int   sidx[CAND_MAX];

    const int row = rbase + blockIdx.x, tid = threadIdx.x;
    const int lane = tid & 31, wid = tid >> 5;
    for (int i = tid; i < DIM; i += 256) xs[i] = g_xc[(size_t)row * DIM + i];
    const int cnt = g_ccnt[row];
    __syncthreads();

    for (int c = wid; c < cnt; c += 8) {
        const int idx = g_cand[(size_t)row * CAND_MAX + c];
        const float* w = g_Wt + (size_t)idx * DIM;
        float a0 = 0.f, a1 = 0.f, a2 = 0.f, a3 = 0.f;
#pragma unroll
        for (int j = 0; j < DIM; j += 128) {
            a0 += xs[j + lane]      * __ldg(w + j + lane);
            a1 += xs[j + lane + 32] * __ldg(w + j + lane + 32);
            a2 += xs[j + lane + 64] * __ldg(w + j + lane + 64);
            a3 += xs[j + lane + 96] * __ldg(w + j + lane + 96);
        }
        float acc = (a0 + a1) + (a2 + a3);
#pragma unroll
        for (int o = 16; o > 0; o >>= 1)
            acc += __shfl_xor_sync(0xffffffffu, acc, o);
        if (lane == 0) {
            float v = fmaxf(acc + bias[idx], 0.f);
            skey[c] = ((unsigned long long)__float_as_uint(v) << 32) |
                      (unsigned)(0xFFFFFFFFu - (unsigned)idx);
            svv[c] = v;
            sidx[c] = idx;
        }
    }
    __syncthreads();

    for (int c = tid; c < cnt; c += 256) {
        const unsigned long long k = skey[c];
        int r = 0;
        for (int j = 0; j < cnt; j++) r += (skey[j] > k);
        if (r < TOPK) {
            g_tidx[row * TOPK + r] = sidx[c];
            g_tval[row * TOPK + r] = svv[c];
        }
    }
}

// ---------------- kernel 6: nested group decode -----------------------------
__global__ __launch_bounds__(256, 1)
void decode_kernel(const float* __restrict__ Wd, const float* __restrict__ bdec,
                   float* __restrict__ out, int rbase) {
    __shared__ int   sidx[TOPK];
    __shared__ float sval[TOPK];
    const int row = rbase + blockIdx.x, tid = threadIdx.x;
    if (tid < TOPK) {
        sidx[tid] = g_tidx[row * TOPK + tid];
        sval[tid] = g_tval[row * TOPK + tid];
    }
    __syncthreads();

    float acc[4];
#pragma unroll
    for (int j = 0; j < 4; j++) acc[j] = bdec[tid + j * 256];

    const int bounds[4] = {0, 2048, 8192, TDICT};
#pragma unroll
    for (int g = 0; g < 3; g++) {
        for (int t = 0; t < TOPK; t++) {
            const int idx = sidx[t];
            if (idx >= bounds[g] && idx < bounds[g + 1]) {
                const float v = sval[t];
                const float* w = Wd + (size_t)idx * DIM;
#pragma unroll
                for (int j = 0; j < 4; j++) acc[j] += v * w[tid + j * 256];
            }
        }
        const size_t o = ((size_t)g * BATCH + row) * DIM;
#pragma unroll
        for (int j = 0; j < 4; j++) out[o + tid + j * 256] = acc[j];
    }
}

// ---------------- launch: chunked with cross-stream overlap -----------------
extern "C" void kernel_launch(void* const* d_in, const int* in_sizes, int n_in,
                              void* d_out, int out_size) {
    const float* x     = (const float*)d_in[0];
    const float* W_enc = (const float*)d_in[1];
    const float* b_enc = (const float*)d_in[2];
    const float* W_dec = (const float*)d_in[3];
    const float* b_dec = (const float*)d_in[4];
    float* out = (float*)d_out;

    static cudaStream_t s2 = nullptr;
    static cudaEvent_t evG[NCHUNK], evDone;
    if (s2 == nullptr) {
        cudaStreamCreateWithFlags(&s2, cudaStreamNonBlocking);
        for (int i = 0; i < NCHUNK; i++)
            cudaEventCreateWithFlags(&evG[i], cudaEventDisableTiming);
        cudaEventCreateWithFlags(&evDone, cudaEventDisableTiming);
    }

    split_x_kernel<<<BATCH * DIM / 256, 256>>>(x, b_dec);
    split_w_kernel<<<dim3(TDICT / 32, DIM / 32), 256>>>(W_enc);

    for (int c = 0; c < NCHUNK; c++) {
        const int rbase = c * CHUNK;
        hgemm_kernel<<<dim3(CHUNK / 128, TDICT / 128), 256>>>(b_enc, rbase);
        cudaEventRecord(evG[c], 0);
        cudaStreamWaitEvent(s2, evG[c], 0);
        topk_approx_kernel<<<CHUNK, 512, 0, s2>>>(rbase);
        refine_kernel<<<CHUNK, 256, 0, s2>>>(b_enc, rbase);
        decode_kernel<<<CHUNK, 256, 0, s2>>>(W_dec, b_dec, out, rbase);
    }
    cudaEventRecord(evDone, s2);
    cudaStreamWaitEvent(0, evDone, 0);
}